// round 4
// baseline (speedup 1.0000x reference)
#include <cuda_runtime.h>
#include <stdint.h>

typedef unsigned long long u64;

// Problem constants (fixed by setup_inputs)
#define En   256      // embedding E
#define Kk   8        // K
#define Bn   8        // batch
#define Tcn  1024     // Tc
#define TTn  24576    // T1 + TLAST (value row length)
#define Mm   2048     // num_mix
#define V1   17       // V+1
#define JV   136      // K * V1
#define JVP  160      // padded: 8 groups * 20 floats (17 used + 3 pad)
#define KSPL 8        // k-splits in g_kernel

// Scratch (static device memory; zero-initialized at load)
__device__ float g_Wf[En * JV];                 // Wf[e][jv]
__device__ float g_Gp[KSPL][Kk * En * JV];      // split-k partials of G
__device__ float g_G[Kk * En * JVP];            // G[jm][f][padded jv]
__device__ float g_dvec[JV];                    // bias vector d[jv]
__device__ int   g_bucket[Bn][Kk][Mm];          // packed (t<<11)|m per (b, jm)
__device__ int   g_cnt[Bn][Kk];

// ---- packed f32x2 helpers (sm_103a) ---------------------------------------
__device__ __forceinline__ u64 pack2(float lo, float hi) {
    u64 r; asm("mov.b64 %0, {%1, %2};" : "=l"(r) : "f"(lo), "f"(hi)); return r;
}
__device__ __forceinline__ void fma2(u64& d, u64 a, u64 b) {
    asm("fma.rn.f32x2 %0, %1, %2, %0;" : "+l"(d) : "l"(a), "l"(b));
}
__device__ __forceinline__ float2 unpack2(u64 v) {
    float2 r; asm("mov.b64 {%0, %1}, %2;" : "=f"(r.x), "=f"(r.y) : "l"(v)); return r;
}

// ---------------------------------------------------------------------------
// Kernel 1: stable compaction of value==2 positions, bucketed by jm = i & 7.
// ---------------------------------------------------------------------------
__global__ void compact_kernel(const unsigned int* __restrict__ v32) {
    int b   = blockIdx.x;
    int tid = threadIdx.x;
    __shared__ int wsum[32];

    if (tid < Kk) g_cnt[b][tid] = 0;

    bool is64 = (v32[1] == 0u);

    int vals[8];
    int c = 0;
    int i0 = tid * 8;
#pragma unroll
    for (int q = 0; q < 8; q++) {
        int i = i0 + q;
        int idx = b * TTn + i;
        int val = is64 ? (int)v32[2 * idx] : (int)v32[idx];
        vals[q] = val;
        c += (val == 2);
    }

    int lane = tid & 31, w = tid >> 5;
    int x = c;
#pragma unroll
    for (int d = 1; d < 32; d <<= 1) {
        int y = __shfl_up_sync(0xffffffffu, x, d);
        if (lane >= d) x += y;
    }
    if (lane == 31) wsum[w] = x;
    __syncthreads();
    if (w == 0) {
        int s = wsum[lane];
#pragma unroll
        for (int d = 1; d < 32; d <<= 1) {
            int y = __shfl_up_sync(0xffffffffu, s, d);
            if (lane >= d) s += y;
        }
        wsum[lane] = s;
    }
    __syncthreads();
    int m = x - c + (w > 0 ? wsum[w - 1] : 0);

#pragma unroll
    for (int q = 0; q < 8; q++) {
        if (vals[q] == 2) {
            int i  = i0 + q;
            int jm = i & 7;
            int t  = i >> 3;
            int slot = atomicAdd(&g_cnt[b][jm], 1);
            g_bucket[b][jm][slot] = (t << 11) | m;
            m++;
        }
    }
}

// ---------------------------------------------------------------------------
// Kernel 2: Wf[e][jv] = sum_o W0[e,o,j] * Wl[v,o]  (2 e-rows/block, padded smem)
// ---------------------------------------------------------------------------
__global__ void wf_kernel(const float* __restrict__ W0, const float* __restrict__ Wl) {
    int e0 = blockIdx.x * 2;
    int tid = threadIdx.x;
    __shared__ float w0s[2][Kk * 264];   // w0s[eo][j*264 + o]
    __shared__ float wls[V1 * 257];      // wls[v*257 + o]

    for (int idx = tid; idx < 2 * En * Kk; idx += blockDim.x) {
        int eo = idx >> 11;
        int r  = idx & 2047;
        int o  = r >> 3, j = r & 7;
        w0s[eo][j * 264 + o] = W0[(e0 + eo) * (En * Kk) + r];
    }
    for (int idx = tid; idx < V1 * En; idx += blockDim.x) {
        int v = idx >> 8, o = idx & 255;
        wls[v * 257 + o] = Wl[idx];
    }
    __syncthreads();

    if (tid < 2 * JV) {
        int eo = tid / JV;
        int jv = tid - eo * JV;
        int j = jv / V1, v = jv - j * V1;
        const float* a = &w0s[eo][j * 264];
        const float* g = &wls[v * 257];
        float s = 0.f;
#pragma unroll 16
        for (int o = 0; o < En; o++)
            s += a[o] * g[o];
        g_Wf[(e0 + eo) * JV + jv] = s;
    }
}

// ---------------------------------------------------------------------------
// Kernel 3: d[jv] = sum_e b1[e]*Wf[e,jv] + sum_o b0[o]*Wl[v,o] + bl[v]
// ---------------------------------------------------------------------------
__global__ void d_kernel(const float* __restrict__ b1, const float* __restrict__ b0,
                         const float* __restrict__ Wl, const float* __restrict__ bl) {
    __shared__ float part[4][JV];
    int tid = threadIdx.x;
    if (tid < 544) {
        int g  = tid / JV;
        int jv = tid - g * JV;
        int v  = jv % V1;
        float s = 0.f;
#pragma unroll 8
        for (int e = g * 64; e < g * 64 + 64; e++)
            s += b1[e] * g_Wf[e * JV + jv];
#pragma unroll 8
        for (int o = g * 64; o < g * 64 + 64; o++)
            s += b0[o] * Wl[v * En + o];
        part[g][jv] = s;
    }
    __syncthreads();
    if (tid < JV) {
        int v = tid % V1;
        g_dvec[tid] = part[0][tid] + part[1][tid] + part[2][tid] + part[3][tid] + bl[v];
    }
}

// ---------------------------------------------------------------------------
// Kernel 4: G partials. G[jm][f][jv] = sum_e W1[f,e,jm] * Wf[e,jv]
// grid (8 f-tiles of 32, 8 jm, 8 k-splits of 32), 256 threads.
// ---------------------------------------------------------------------------
__global__ __launch_bounds__(256) void g_kernel(const float* __restrict__ W1) {
    int f0 = blockIdx.x * 32;
    int jm = blockIdx.y;
    int kbase = blockIdx.z * 32;
    int tid = threadIdx.x;
    int ty = tid >> 3;   // f row 0..31
    int tx = tid & 7;    // column group

    __shared__ float As[32][33];       // As[e][f]
    __shared__ float Wfs[32 * JVP];    // padded

    for (int idx = tid; idx < 32 * 32; idx += 256) {
        int e  = idx & 31;
        int fr = idx >> 5;
        As[e][fr] = W1[(f0 + fr) * (En * Kk) + (kbase + e) * Kk + jm];
    }
    for (int idx = tid; idx < 32 * JV; idx += 256) {
        int e  = idx / JV;
        int jv = idx - e * JV;
        int t  = jv / V1;
        int ic = jv - t * V1;
        Wfs[e * JVP + t * 20 + ic] = g_Wf[(kbase + e) * JV + jv];
    }
    __syncthreads();

    float acc[V1];
#pragma unroll
    for (int i = 0; i < V1; i++) acc[i] = 0.f;

    const float4* Wfs4 = reinterpret_cast<const float4*>(Wfs);
#pragma unroll 4
    for (int kk = 0; kk < 32; kk++) {
        float a = As[kk][ty];
        int base4 = (kk * JVP + tx * 20) >> 2;
        float4 v0 = Wfs4[base4 + 0];
        float4 v1 = Wfs4[base4 + 1];
        float4 v2 = Wfs4[base4 + 2];
        float4 v3 = Wfs4[base4 + 3];
        float  v4 = Wfs[kk * JVP + tx * 20 + 16];
        acc[0]  += a * v0.x;  acc[1]  += a * v0.y;  acc[2]  += a * v0.z;  acc[3]  += a * v0.w;
        acc[4]  += a * v1.x;  acc[5]  += a * v1.y;  acc[6]  += a * v1.z;  acc[7]  += a * v1.w;
        acc[8]  += a * v2.x;  acc[9]  += a * v2.y;  acc[10] += a * v2.z;  acc[11] += a * v2.w;
        acc[12] += a * v3.x;  acc[13] += a * v3.y;  acc[14] += a * v3.z;  acc[15] += a * v3.w;
        acc[16] += a * v4;
    }

    // Stage in smem (reuse Wfs) for coalesced global store of the partial.
    __syncthreads();
#pragma unroll
    for (int i = 0; i < V1; i++)
        Wfs[ty * JV + tx * V1 + i] = acc[i];
    __syncthreads();
    float* dst = &g_Gp[blockIdx.z][(jm * En + f0) * JV];
    for (int idx = tid; idx < 32 * JV; idx += 256)
        dst[idx] = Wfs[idx];
}

// ---------------------------------------------------------------------------
// Kernel 4b: reduce 8 partials into padded G layout.
// ---------------------------------------------------------------------------
__global__ void g_reduce_kernel() {
    int i = blockIdx.x * 1024 + threadIdx.x;
    if (i >= Kk * En * JV) return;
    float v = 0.f;
#pragma unroll
    for (int s = 0; s < KSPL; s++) v += g_Gp[s][i];
    int row = i / JV;
    int jv  = i - row * JV;
    int t   = jv / V1;
    int ic  = jv - t * V1;
    g_G[row * JVP + t * 20 + ic] = v;
}

// ---------------------------------------------------------------------------
// Kernel 5: main gather-GEMM with packed f32x2 math.
// out[(b*2048+m)*136 + tx*17+i] = sum_f x[b,t_m,f] * G[jm][f][.] + d
// grid (32 row-tiles of 64, 8 jm, 8 b), 256 threads; TM=2, 9 packed col-pairs.
// ---------------------------------------------------------------------------
__global__ __launch_bounds__(256) void main_kernel(const float* __restrict__ x,
                                                   float* __restrict__ out) {
    int b  = blockIdx.z;
    int jm = blockIdx.y;
    int count = g_cnt[b][jm];
    int r0 = blockIdx.x * 64;
    if (r0 >= count) return;

    int tid = threadIdx.x;
    int ty = tid >> 3;   // 0..31 (rows ty*2, ty*2+1)
    int tx = tid & 7;    // column group

    __shared__ int   Es[64];
    __shared__ float Xs[32][65];      // [k][r]
    __shared__ float Gs[32 * JVP];

    if (tid < 64) {
        int r = r0 + tid;
        Es[tid] = (r < count) ? g_bucket[b][jm][r] : 0;
    }
    __syncthreads();

    // bias folded into accumulator init
    float dv[V1];
#pragma unroll
    for (int i = 0; i < V1; i++) dv[i] = g_dvec[tx * V1 + i];
    u64 acc[2][9];
#pragma unroll
    for (int p = 0; p < 8; p++) {
        u64 dp = pack2(dv[2 * p], dv[2 * p + 1]);
        acc[0][p] = dp; acc[1][p] = dp;
    }
    {
        u64 dp = pack2(dv[16], 0.f);
        acc[0][8] = dp; acc[1][8] = dp;
    }

    const float* xb = x + (size_t)b * Tcn * En;
    const float* Gj = g_G + jm * En * JVP;

    for (int kc = 0; kc < En; kc += 32) {
#pragma unroll
        for (int idx = tid; idx < 64 * 32; idx += 256) {
            int r = idx >> 5, k = idx & 31;
            int t = Es[r] >> 11;
            Xs[k][r] = xb[t * En + kc + k];
        }
        {
            const float4* s4 = reinterpret_cast<const float4*>(Gj + kc * JVP);
            float4* d4 = reinterpret_cast<float4*>(Gs);
#pragma unroll
            for (int idx = tid; idx < (32 * JVP) / 4; idx += 256)
                d4[idx] = s4[idx];
        }
        __syncthreads();
#pragma unroll
        for (int kk = 0; kk < 32; kk++) {
            float a0f = Xs[kk][ty * 2 + 0];
            float a1f = Xs[kk][ty * 2 + 1];
            u64 A0 = pack2(a0f, a0f);
            u64 A1 = pack2(a1f, a1f);
            const ulonglong2* gq = reinterpret_cast<const ulonglong2*>(Gs + kk * JVP + tx * 20);
            ulonglong2 q0 = gq[0];
            ulonglong2 q1 = gq[1];
            ulonglong2 q2 = gq[2];
            ulonglong2 q3 = gq[3];
            u64 g8 = *reinterpret_cast<const u64*>(Gs + kk * JVP + tx * 20 + 16);
            fma2(acc[0][0], A0, q0.x); fma2(acc[1][0], A1, q0.x);
            fma2(acc[0][1], A0, q0.y); fma2(acc[1][1], A1, q0.y);
            fma2(acc[0][2], A0, q1.x); fma2(acc[1][2], A1, q1.x);
            fma2(acc[0][3], A0, q1.y); fma2(acc[1][3], A1, q1.y);
            fma2(acc[0][4], A0, q2.x); fma2(acc[1][4], A1, q2.x);
            fma2(acc[0][5], A0, q2.y); fma2(acc[1][5], A1, q2.y);
            fma2(acc[0][6], A0, q3.x); fma2(acc[1][6], A1, q3.x);
            fma2(acc[0][7], A0, q3.y); fma2(acc[1][7], A1, q3.y);
            fma2(acc[0][8], A0, g8);   fma2(acc[1][8], A1, g8);
        }
        __syncthreads();
    }

#pragma unroll
    for (int j = 0; j < 2; j++) {
        int r = ty * 2 + j;
        if (r0 + r < count) {
            int m = Es[r] & 0x7FF;
            float* op = out + (size_t)(b * Mm + m) * JV + tx * V1;
#pragma unroll
            for (int p = 0; p < 8; p++) {
                float2 v = unpack2(acc[j][p]);
                op[2 * p]     = v.x;
                op[2 * p + 1] = v.y;
            }
            op[16] = unpack2(acc[j][8]).x;
        }
    }
}

// ---------------------------------------------------------------------------
extern "C" void kernel_launch(void* const* d_in, const int* in_sizes, int n_in,
                              void* d_out, int out_size) {
    const float*        x     = (const float*)d_in[0];
    const unsigned int* value = (const unsigned int*)d_in[1];

    int wi = 4;
    while (wi < n_in && in_sizes[wi] != En * En * Kk) wi++;
    const float* W1 = (const float*)d_in[wi + 0];
    const float* b1 = (const float*)d_in[wi + 1];
    const float* W0 = (const float*)d_in[wi + 2];
    const float* b0 = (const float*)d_in[wi + 3];
    const float* Wl = (const float*)d_in[wi + 4];
    const float* bl = (const float*)d_in[wi + 5];
    float* out = (float*)d_out;

    compact_kernel<<<Bn, 1024>>>(value);
    wf_kernel<<<128, 272>>>(W0, Wl);
    d_kernel<<<1, 544>>>(b1, b0, Wl, bl);
    g_kernel<<<dim3(8, Kk, KSPL), 256>>>(W1);
    g_reduce_kernel<<<(Kk * En * JV + 1023) / 1024, 1024>>>();
    main_kernel<<<dim3(32, Kk, Bn), 256>>>(x, out);
}

// round 5
// speedup vs baseline: 1.0181x; 1.0181x over previous
#include <cuda_runtime.h>
#include <stdint.h>

typedef unsigned long long u64;

// Problem constants (fixed by setup_inputs)
#define En   256      // embedding E
#define Kk   8        // K
#define Bn   8        // batch
#define Tcn  1024     // Tc
#define TTn  24576    // T1 + TLAST (value row length)
#define Mm   2048     // num_mix
#define V1   17       // V+1
#define JV   136      // K * V1
#define JVP  160      // padded: 8 groups * 20 floats (17 used + 3 pad)
#define KSPL 8        // k-splits in g_kernel

// Scratch (static device memory; zero-initialized at load)
__device__ float g_Wf[En * JVP];                // Wf[e][j*20+v]  (padded)
__device__ float g_Gp[KSPL][Kk * En * JVP];     // split-k partials of G (padded)
__device__ float g_G[Kk * En * JVP];            // G[jm][f][padded jv]
__device__ float g_dvec[JV];                    // bias vector d[jv] (linear)
__device__ int   g_bucket[Bn][Kk][Mm];          // packed (t<<11)|m per (b, jm)
__device__ int   g_cnt[Bn][Kk];

// ---- packed f32x2 helpers (sm_103a) ---------------------------------------
__device__ __forceinline__ u64 pack2(float lo, float hi) {
    u64 r; asm("mov.b64 %0, {%1, %2};" : "=l"(r) : "f"(lo), "f"(hi)); return r;
}
__device__ __forceinline__ void fma2(u64& d, u64 a, u64 b) {
    asm("fma.rn.f32x2 %0, %1, %2, %0;" : "+l"(d) : "l"(a), "l"(b));
}
__device__ __forceinline__ float2 unpack2(u64 v) {
    float2 r; asm("mov.b64 {%0, %1}, %2;" : "=f"(r.x), "=f"(r.y) : "l"(v)); return r;
}

// ---------------------------------------------------------------------------
// Kernel 1: stable compaction of value==2 positions, bucketed by jm = i & 7.
// ---------------------------------------------------------------------------
__global__ void compact_kernel(const unsigned int* __restrict__ v32) {
    int b   = blockIdx.x;
    int tid = threadIdx.x;
    __shared__ int wsum[32];

    if (tid < Kk) g_cnt[b][tid] = 0;

    bool is64 = (v32[1] == 0u);

    int vals[8];
    int c = 0;
    int i0 = tid * 8;
#pragma unroll
    for (int q = 0; q < 8; q++) {
        int i = i0 + q;
        int idx = b * TTn + i;
        int val = is64 ? (int)v32[2 * idx] : (int)v32[idx];
        vals[q] = val;
        c += (val == 2);
    }

    int lane = tid & 31, w = tid >> 5;
    int x = c;
#pragma unroll
    for (int d = 1; d < 32; d <<= 1) {
        int y = __shfl_up_sync(0xffffffffu, x, d);
        if (lane >= d) x += y;
    }
    if (lane == 31) wsum[w] = x;
    __syncthreads();
    if (w == 0) {
        int s = wsum[lane];
#pragma unroll
        for (int d = 1; d < 32; d <<= 1) {
            int y = __shfl_up_sync(0xffffffffu, s, d);
            if (lane >= d) s += y;
        }
        wsum[lane] = s;
    }
    __syncthreads();
    int m = x - c + (w > 0 ? wsum[w - 1] : 0);

#pragma unroll
    for (int q = 0; q < 8; q++) {
        if (vals[q] == 2) {
            int i  = i0 + q;
            int jm = i & 7;
            int t  = i >> 3;
            int slot = atomicAdd(&g_cnt[b][jm], 1);
            g_bucket[b][jm][slot] = (t << 11) | m;
            m++;
        }
    }
}

// ---------------------------------------------------------------------------
// Kernel 2: Wf[e][j*20+v] = sum_o W0[e,o,j] * Wl[v,o]  (padded output layout)
// ---------------------------------------------------------------------------
__global__ void wf_kernel(const float* __restrict__ W0, const float* __restrict__ Wl) {
    int e0 = blockIdx.x * 2;
    int tid = threadIdx.x;
    __shared__ float w0s[2][Kk * 264];   // w0s[eo][j*264 + o]
    __shared__ float wls[V1 * 257];      // wls[v*257 + o]

    for (int idx = tid; idx < 2 * En * Kk; idx += blockDim.x) {
        int eo = idx >> 11;
        int r  = idx & 2047;
        int o  = r >> 3, j = r & 7;
        w0s[eo][j * 264 + o] = W0[(e0 + eo) * (En * Kk) + r];
    }
    for (int idx = tid; idx < V1 * En; idx += blockDim.x) {
        int v = idx >> 8, o = idx & 255;
        wls[v * 257 + o] = Wl[idx];
    }
    __syncthreads();

    if (tid < 2 * JV) {
        int eo = tid / JV;
        int jv = tid - eo * JV;
        int j = jv / V1, v = jv - j * V1;
        const float* a = &w0s[eo][j * 264];
        const float* g = &wls[v * 257];
        float s = 0.f;
#pragma unroll 16
        for (int o = 0; o < En; o++)
            s += a[o] * g[o];
        g_Wf[(e0 + eo) * JVP + j * 20 + v] = s;
    }
}

// ---------------------------------------------------------------------------
// Kernel 3: d[jv] = sum_e b1[e]*Wf[e,jv] + sum_o b0[o]*Wl[v,o] + bl[v]
// ---------------------------------------------------------------------------
__global__ void d_kernel(const float* __restrict__ b1, const float* __restrict__ b0,
                         const float* __restrict__ Wl, const float* __restrict__ bl) {
    __shared__ float part[4][JV];
    int tid = threadIdx.x;
    if (tid < 544) {
        int g  = tid / JV;
        int jv = tid - g * JV;
        int j  = jv / V1, v = jv - j * V1;
        float s = 0.f;
#pragma unroll 8
        for (int e = g * 64; e < g * 64 + 64; e++)
            s += b1[e] * g_Wf[e * JVP + j * 20 + v];
#pragma unroll 8
        for (int o = g * 64; o < g * 64 + 64; o++)
            s += b0[o] * Wl[v * En + o];
        part[g][jv] = s;
    }
    __syncthreads();
    if (tid < JV) {
        int v = tid % V1;
        g_dvec[tid] = part[0][tid] + part[1][tid] + part[2][tid] + part[3][tid] + bl[v];
    }
}

// ---------------------------------------------------------------------------
// Kernel 4: G partials. G[jm][f][.] = sum_e W1[f,e,jm] * Wf[e][.]
// grid (8 f-tiles of 32, 8 jm, 8 k-splits of 32), 256 threads.
// All layouts padded: staging is pure float4 memcpy, zero integer division.
// ---------------------------------------------------------------------------
__global__ __launch_bounds__(256) void g_kernel(const float* __restrict__ W1) {
    int f0 = blockIdx.x * 32;
    int jm = blockIdx.y;
    int kbase = blockIdx.z * 32;
    int tid = threadIdx.x;
    int ty = tid >> 3;   // f row 0..31
    int tx = tid & 7;    // column group

    __shared__ float As[32][33];       // As[e][f]
    __shared__ float Wfs[32 * JVP];    // padded

    // A tile: strided gather of W1 (L2-friendly across the 8 jm blocks)
    for (int idx = tid; idx < 32 * 32; idx += 256) {
        int e  = idx & 31;
        int fr = idx >> 5;
        As[e][fr] = W1[(f0 + fr) * (En * Kk) + (kbase + e) * Kk + jm];
    }
    // Wf tile: straight float4 copy (padded layout)
    {
        const float4* s4 = reinterpret_cast<const float4*>(g_Wf + kbase * JVP);
        float4* d4 = reinterpret_cast<float4*>(Wfs);
#pragma unroll
        for (int idx = tid; idx < (32 * JVP) / 4; idx += 256)
            d4[idx] = s4[idx];
    }
    __syncthreads();

    u64 acc[9];
#pragma unroll
    for (int p = 0; p < 9; p++) acc[p] = 0ull;

    const float* gbase = Wfs + tx * 20;
#pragma unroll 4
    for (int kk = 0; kk < 32; kk++) {
        float a = As[kk][ty];
        u64 A = pack2(a, a);
        const ulonglong2* gq = reinterpret_cast<const ulonglong2*>(gbase + kk * JVP);
        ulonglong2 q0 = gq[0];
        ulonglong2 q1 = gq[1];
        ulonglong2 q2 = gq[2];
        ulonglong2 q3 = gq[3];
        u64 g8 = *reinterpret_cast<const u64*>(gbase + kk * JVP + 16);
        fma2(acc[0], A, q0.x);
        fma2(acc[1], A, q0.y);
        fma2(acc[2], A, q1.x);
        fma2(acc[3], A, q1.y);
        fma2(acc[4], A, q2.x);
        fma2(acc[5], A, q2.y);
        fma2(acc[6], A, q3.x);
        fma2(acc[7], A, q3.y);
        fma2(acc[8], A, g8);
    }

    // Stage results padded in smem (reuse Wfs), then float4 copy out.
    __syncthreads();
    {
        float* dstr = Wfs + ty * JVP + tx * 20;
#pragma unroll
        for (int p = 0; p < 8; p++) {
            float2 v = unpack2(acc[p]);
            dstr[2 * p]     = v.x;
            dstr[2 * p + 1] = v.y;
        }
        dstr[16] = unpack2(acc[8]).x;
        dstr[17] = 0.f; dstr[18] = 0.f; dstr[19] = 0.f;
    }
    __syncthreads();
    {
        float4* dst4 = reinterpret_cast<float4*>(&g_Gp[blockIdx.z][(jm * En + f0) * JVP]);
        const float4* s4 = reinterpret_cast<const float4*>(Wfs);
#pragma unroll
        for (int idx = tid; idx < (32 * JVP) / 4; idx += 256)
            dst4[idx] = s4[idx];
    }
}

// ---------------------------------------------------------------------------
// Kernel 4b: reduce 8 padded partials into g_G (pure linear float4 adds).
// ---------------------------------------------------------------------------
__global__ void g_reduce_kernel() {
    int i = blockIdx.x * 1024 + threadIdx.x;
    if (i >= (Kk * En * JVP) / 4) return;
    float4 v = reinterpret_cast<const float4*>(g_Gp[0])[i];
#pragma unroll
    for (int s = 1; s < KSPL; s++) {
        float4 p = reinterpret_cast<const float4*>(g_Gp[s])[i];
        v.x += p.x; v.y += p.y; v.z += p.z; v.w += p.w;
    }
    reinterpret_cast<float4*>(g_G)[i] = v;
}

// ---------------------------------------------------------------------------
// Kernel 5: main gather-GEMM with packed f32x2 math, pre-duplicated A operand.
// grid (32 row-tiles of 64, 8 jm, 8 b), 256 threads; TM=2, 9 packed col-pairs.
// ---------------------------------------------------------------------------
__global__ __launch_bounds__(256) void main_kernel(const float* __restrict__ x,
                                                   float* __restrict__ out) {
    int b  = blockIdx.z;
    int jm = blockIdx.y;
    int count = g_cnt[b][jm];
    int r0 = blockIdx.x * 64;
    if (r0 >= count) return;

    int tid = threadIdx.x;
    int ty = tid >> 3;   // 0..31 (rows ty*2, ty*2+1)
    int tx = tid & 7;    // column group

    __shared__ int   Es[64];
    __shared__ u64   Xs2[32][65];     // [k][r] duplicated {v,v}
    __shared__ float Gs[32 * JVP];

    if (tid < 64) {
        int r = r0 + tid;
        Es[tid] = (r < count) ? g_bucket[b][jm][r] : 0;
    }
    __syncthreads();

    // bias folded into accumulator init
    u64 acc[2][9];
    {
        const float* dvp = g_dvec + tx * V1;
#pragma unroll
        for (int p = 0; p < 8; p++) {
            u64 dp = pack2(dvp[2 * p], dvp[2 * p + 1]);
            acc[0][p] = dp; acc[1][p] = dp;
        }
        u64 dp = pack2(dvp[16], 0.f);
        acc[0][8] = dp; acc[1][8] = dp;
    }

    const float* xb = x + (size_t)b * Tcn * En;
    const float* Gj = g_G + jm * En * JVP;

    for (int kc = 0; kc < En; kc += 32) {
#pragma unroll
        for (int idx = tid; idx < 64 * 32; idx += 256) {
            int r = idx >> 5, k = idx & 31;
            int t = Es[r] >> 11;
            float v = xb[t * En + kc + k];
            Xs2[k][r] = pack2(v, v);
        }
        {
            const float4* s4 = reinterpret_cast<const float4*>(Gj + kc * JVP);
            float4* d4 = reinterpret_cast<float4*>(Gs);
#pragma unroll
            for (int idx = tid; idx < (32 * JVP) / 4; idx += 256)
                d4[idx] = s4[idx];
        }
        __syncthreads();
        const float* gbase = Gs + tx * 20;
#pragma unroll
        for (int kk = 0; kk < 32; kk++) {
            u64 A0 = Xs2[kk][ty * 2 + 0];
            u64 A1 = Xs2[kk][ty * 2 + 1];
            const ulonglong2* gq = reinterpret_cast<const ulonglong2*>(gbase + kk * JVP);
            ulonglong2 q0 = gq[0];
            ulonglong2 q1 = gq[1];
            ulonglong2 q2 = gq[2];
            ulonglong2 q3 = gq[3];
            u64 g8 = *reinterpret_cast<const u64*>(gbase + kk * JVP + 16);
            fma2(acc[0][0], A0, q0.x); fma2(acc[1][0], A1, q0.x);
            fma2(acc[0][1], A0, q0.y); fma2(acc[1][1], A1, q0.y);
            fma2(acc[0][2], A0, q1.x); fma2(acc[1][2], A1, q1.x);
            fma2(acc[0][3], A0, q1.y); fma2(acc[1][3], A1, q1.y);
            fma2(acc[0][4], A0, q2.x); fma2(acc[1][4], A1, q2.x);
            fma2(acc[0][5], A0, q2.y); fma2(acc[1][5], A1, q2.y);
            fma2(acc[0][6], A0, q3.x); fma2(acc[1][6], A1, q3.x);
            fma2(acc[0][7], A0, q3.y); fma2(acc[1][7], A1, q3.y);
            fma2(acc[0][8], A0, g8);   fma2(acc[1][8], A1, g8);
        }
        __syncthreads();
    }

#pragma unroll
    for (int j = 0; j < 2; j++) {
        int r = ty * 2 + j;
        if (r0 + r < count) {
            int m = Es[r] & 0x7FF;
            float* op = out + (size_t)(b * Mm + m) * JV + tx * V1;
#pragma unroll
            for (int p = 0; p < 8; p++) {
                float2 v = unpack2(acc[j][p]);
                op[2 * p]     = v.x;
                op[2 * p + 1] = v.y;
            }
            op[16] = unpack2(acc[j][8]).x;
        }
    }
}

// ---------------------------------------------------------------------------
extern "C" void kernel_launch(void* const* d_in, const int* in_sizes, int n_in,
                              void* d_out, int out_size) {
    const float*        x     = (const float*)d_in[0];
    const unsigned int* value = (const unsigned int*)d_in[1];

    int wi = 4;
    while (wi < n_in && in_sizes[wi] != En * En * Kk) wi++;
    const float* W1 = (const float*)d_in[wi + 0];
    const float* b1 = (const float*)d_in[wi + 1];
    const float* W0 = (const float*)d_in[wi + 2];
    const float* b0 = (const float*)d_in[wi + 3];
    const float* Wl = (const float*)d_in[wi + 4];
    const float* bl = (const float*)d_in[wi + 5];
    float* out = (float*)d_out;

    compact_kernel<<<Bn, 1024>>>(value);
    wf_kernel<<<128, 272>>>(W0, Wl);
    d_kernel<<<1, 544>>>(b1, b0, Wl, bl);
    g_kernel<<<dim3(8, Kk, KSPL), 256>>>(W1);
    g_reduce_kernel<<<(Kk * En * JVP / 4 + 1023) / 1024, 1024>>>();
    main_kernel<<<dim3(32, Kk, Bn), 256>>>(x, out);
}